// round 6
// baseline (speedup 1.0000x reference)
#include <cuda_runtime.h>
#include <cstdint>

#define SQ 512
#define NB 64
#define NH 1024
#define NI 256
#define NG 4096
#define HSEQ ((size_t)SQ*NB*NH)

// scratch (no allocations allowed): xg = x@Wx + bx + bh, and per-step sync flags
__device__ float g_xg[(size_t)SQ*NB*NG];
__device__ int g_flags[SQ];

__device__ __forceinline__ unsigned tf32u(float x){
  unsigned u; asm("cvt.rna.tf32.f32 %0, %1;" : "=r"(u) : "f"(x)); return u;
}
__device__ __forceinline__ void mma8(float d[4], unsigned a0,unsigned a1,unsigned a2,unsigned a3,
                                     unsigned b0,unsigned b1){
  asm("mma.sync.aligned.m16n8k8.row.col.f32.tf32.tf32.f32 "
      "{%0,%1,%2,%3},{%4,%5,%6,%7},{%8,%9},{%0,%1,%2,%3};"
      : "+f"(d[0]),"+f"(d[1]),"+f"(d[2]),"+f"(d[3])
      : "r"(a0),"r"(a1),"r"(a2),"r"(a3),"r"(b0),"r"(b1));
}
__device__ __forceinline__ float sigf(float x){ return 1.f/(1.f+expf(-x)); }

__global__ void zero_flags(){ g_flags[threadIdx.x]=0; }

// ---------------------------------------------------------------------------
// Phase 1: xg[m][gate*1024+j] = x[m,:] @ Wgate[:, j] + bx + bh
// CTA tile 128(M) x 64(N), K=256 in 8 chunks of 32. 8 warps = 4(m) x 2(n).
// ---------------------------------------------------------------------------
__global__ void __launch_bounds__(256) xg_gemm(
    const float* __restrict__ x,
    const float* __restrict__ Wa,const float* __restrict__ Wb,
    const float* __restrict__ Wc,const float* __restrict__ Wd,
    const float* __restrict__ xa,const float* __restrict__ xb,
    const float* __restrict__ xc,const float* __restrict__ xd,
    const float* __restrict__ ha,const float* __restrict__ hb,
    const float* __restrict__ hc,const float* __restrict__ hd)
{
  __shared__ float As[128*36];   // pad 36 -> conflict-free A-frag LDS
  __shared__ float Bs[32*72];    // pad 72 -> conflict-free B-frag LDS
  __shared__ float bias[64];
  const int tid=threadIdx.x, w=tid>>5, lane=tid&31;
  const int g=lane>>2, tg=lane&3, wm=w>>1, wn=w&1;
  const int mbase=blockIdx.y*128, nb=blockIdx.x*64;
  const int gate=nb>>10, colbase=nb&1023;
  const float* Wg = gate==0?Wa:gate==1?Wb:gate==2?Wc:Wd;
  const float* bx = gate==0?xa:gate==1?xb:gate==2?xc:xd;
  const float* bh = gate==0?ha:gate==1?hb:gate==2?hc:hd;
  if (tid<64) bias[tid]=bx[colbase+tid]+bh[colbase+tid];

  float acc[2][4][4];
  #pragma unroll
  for(int i=0;i<2;i++)
    #pragma unroll
    for(int j=0;j<4;j++)
      #pragma unroll
      for(int e=0;e<4;e++) acc[i][j][e]=0.f;

  for(int kc=0;kc<8;kc++){
    #pragma unroll
    for(int p=0;p<4;p++){             // stage A: 128 rows x 32 k (tf32)
      int fid=tid+p*256, row=fid>>3, c4=(fid&7)*4;
      float4 v=*(const float4*)(x+(size_t)(mbase+row)*NI+kc*32+c4);
      v.x=__uint_as_float(tf32u(v.x)); v.y=__uint_as_float(tf32u(v.y));
      v.z=__uint_as_float(tf32u(v.z)); v.w=__uint_as_float(tf32u(v.w));
      *(float4*)(As+row*36+c4)=v;
    }
    #pragma unroll
    for(int p=0;p<2;p++){             // stage B: 32 k x 64 cols (tf32)
      int fid=tid+p*256, r=fid>>4, c4=(fid&15)*4;
      float4 v=*(const float4*)(Wg+(size_t)(kc*32+r)*NH+colbase+c4);
      v.x=__uint_as_float(tf32u(v.x)); v.y=__uint_as_float(tf32u(v.y));
      v.z=__uint_as_float(tf32u(v.z)); v.w=__uint_as_float(tf32u(v.w));
      *(float4*)(Bs+r*72+c4)=v;
    }
    __syncthreads();
    #pragma unroll
    for(int kk=0;kk<4;kk++){
      unsigned a[2][4];
      #pragma unroll
      for(int mt=0;mt<2;mt++){
        int ar=wm*32+mt*16+g, k0=kk*8+tg;
        a[mt][0]=__float_as_uint(As[ar*36+k0]);
        a[mt][1]=__float_as_uint(As[(ar+8)*36+k0]);
        a[mt][2]=__float_as_uint(As[ar*36+k0+4]);
        a[mt][3]=__float_as_uint(As[(ar+8)*36+k0+4]);
      }
      #pragma unroll
      for(int nt=0;nt<4;nt++){
        int nc=wn*32+nt*8+g, k0=kk*8+tg;
        unsigned b0=__float_as_uint(Bs[k0*72+nc]);
        unsigned b1=__float_as_uint(Bs[(k0+4)*72+nc]);
        mma8(acc[0][nt],a[0][0],a[0][1],a[0][2],a[0][3],b0,b1);
        mma8(acc[1][nt],a[1][0],a[1][1],a[1][2],a[1][3],b0,b1);
      }
    }
    __syncthreads();
  }
  #pragma unroll
  for(int mt=0;mt<2;mt++){
    #pragma unroll
    for(int nt=0;nt<4;nt++){
      int row0=mbase+wm*32+mt*16+g;
      int colL=wn*32+nt*8+2*tg;
      float b0v=bias[colL], b1v=bias[colL+1];
      float* o0=g_xg+(size_t)row0*NG+nb+colL;
      *(float2*)o0               = make_float2(acc[mt][nt][0]+b0v, acc[mt][nt][1]+b1v);
      *(float2*)(o0+(size_t)8*NG)= make_float2(acc[mt][nt][2]+b0v, acc[mt][nt][3]+b1v);
    }
  }
}

// ---------------------------------------------------------------------------
// Phase 2: persistent recurrence. 128 CTAs, CTA c owns h-cols [8c,8c+8) and
// the matching 8 cols of each gate (N-slice 32). Wh slice pre-packed into
// B-fragment order in smem; h read straight from h_seq[t-1] via LDG;
// c-state and gate math in registers. Grid sync via g_flags counters.
// Warp w: m-tile (w&3), k-half (w>>2); smem reduction combines k-halves.
// ---------------------------------------------------------------------------
__global__ void __launch_bounds__(256) lstm_rec(
    const float* __restrict__ Wh1,const float* __restrict__ Wh2,
    const float* __restrict__ Wh3,const float* __restrict__ Wh4,
    float* __restrict__ out)
{
  extern __shared__ float sm[];
  float* Bp  = sm;            // 32768 floats: packed B frags (128 KB)
  float* red = sm+32768;      // 2048 floats: k-half reduction (8 KB)
  const int tid=threadIdx.x, w=tid>>5, lane=tid&31;
  const int g=lane>>2, tg=lane&3, mt=w&3, kh=w>>2, cta=blockIdx.x;

  { // one-time pack: Bp[(s*2+p)*32+ln)*4+e] = tf32(W_{2p+(e>>1)}[8s+tg'+4*(e&1)][8c+g'])
    const float* Whs[4]={Wh1,Wh2,Wh3,Wh4};
    for(int idx=tid; idx<32768; idx+=256){
      int e=idx&3, ln=(idx>>2)&31, p=(idx>>7)&1, s=idx>>8;
      int nt=2*p+(e>>1);
      int k=8*s+(ln&3)+4*(e&1);
      int col=8*cta+(ln>>2);
      Bp[idx]=__uint_as_float(tf32u(Whs[nt][(size_t)k*NH+col]));
    }
  }
  __syncthreads();

  float cst[4]={0,0,0,0}, hv[4]={0,0,0,0};
  const int r0=16*mt+g;

  #pragma unroll 1
  for(int t=0;t<SQ;t++){
    float acc[4][4];
    #pragma unroll
    for(int i=0;i<4;i++)
      #pragma unroll
      for(int e=0;e<4;e++) acc[i][e]=0.f;

    if(t>0){
      if(tid==0){
        volatile int* f=&g_flags[t-1];
        while(*f!=128) __nanosleep(32);
      }
      __syncthreads();
      __threadfence();   // acquire: order subsequent h loads after flag observe
      const float* hp = out + (size_t)(t-1)*NB*NH + (size_t)r0*NH + kh*512;
      const float4* Bq = (const float4*)Bp;
      #pragma unroll 4
      for(int s=0;s<64;s++){
        unsigned a0=tf32u(hp[8*s+tg]);
        unsigned a1=tf32u(hp[8*NH+8*s+tg]);
        unsigned a2=tf32u(hp[8*s+tg+4]);
        unsigned a3=tf32u(hp[8*NH+8*s+tg+4]);
        int sg=kh*64+s;
        float4 B0=Bq[(sg*2+0)*32+lane];
        float4 B1=Bq[(sg*2+1)*32+lane];
        mma8(acc[0],a0,a1,a2,a3,__float_as_uint(B0.x),__float_as_uint(B0.y));
        mma8(acc[1],a0,a1,a2,a3,__float_as_uint(B0.z),__float_as_uint(B0.w));
        mma8(acc[2],a0,a1,a2,a3,__float_as_uint(B1.x),__float_as_uint(B1.y));
        mma8(acc[3],a0,a1,a2,a3,__float_as_uint(B1.z),__float_as_uint(B1.w));
      }
    }
    __syncthreads();
    if(kh==1){
      #pragma unroll
      for(int i=0;i<4;i++)
        #pragma unroll
        for(int e=0;e<4;e++) red[(i*128+mt*32+lane)*4+e]=acc[i][e];
    }
    __syncthreads();
    if(kh==0){
      #pragma unroll
      for(int i=0;i<4;i++)
        #pragma unroll
        for(int e=0;e<4;e++) acc[i][e]+=red[(i*128+mt*32+lane)*4+e];
      // add xg, gate nonlinearities, state update — all in registers
      const float* xbp = g_xg + ((size_t)t*NB+r0)*NG + 8*cta + 2*tg;
      float gv[4][4];
      #pragma unroll
      for(int nt=0;nt<4;nt++){
        float2 x0=*(const float2*)(xbp+nt*NH);
        float2 x1=*(const float2*)(xbp+(size_t)8*NG+nt*NH);
        gv[nt][0]=acc[nt][0]+x0.x; gv[nt][1]=acc[nt][1]+x0.y;
        gv[nt][2]=acc[nt][2]+x1.x; gv[nt][3]=acc[nt][3]+x1.y;
      }
      #pragma unroll
      for(int e=0;e<4;e++){
        float f =sigf(gv[0][e]), ii=sigf(gv[1][e]);
        float o =sigf(gv[2][e]), cd=tanhf(gv[3][e]);
        cst[e]=f*cst[e]+ii*cd;
        hv[e]=o*tanhf(cst[e]);
      }
      float* hw = out + ((size_t)t*NB+r0)*NH + 8*cta + 2*tg;
      *(float2*)hw               = make_float2(hv[0],hv[1]);
      *(float2*)(hw+(size_t)8*NH)= make_float2(hv[2],hv[3]);
    }
    __threadfence();   // release: h_seq[t] visible before flag arrival
    __syncthreads();
    if(tid==0) atomicAdd(&g_flags[t],1);
  }

  if(kh==0){ // tails: h_final (== h_seq[511]) then c_final
    float* ho = out + HSEQ + (size_t)r0*NH + 8*cta + 2*tg;
    float* co = ho + (size_t)NB*NH;
    *(float2*)ho               = make_float2(hv[0],hv[1]);
    *(float2*)(ho+(size_t)8*NH)= make_float2(hv[2],hv[3]);
    *(float2*)co               = make_float2(cst[0],cst[1]);
    *(float2*)(co+(size_t)8*NH)= make_float2(cst[2],cst[3]);
  }
}

extern "C" void kernel_launch(void* const* d_in, const int* in_sizes, int n_in,
                              void* d_out, int out_size){
  const float* x =(const float*)d_in[0];
  const float* W1=(const float*)d_in[1];  const float* b1=(const float*)d_in[2];
  const float* W2=(const float*)d_in[3];  const float* b2=(const float*)d_in[4];
  const float* W3=(const float*)d_in[5];  const float* b3=(const float*)d_in[6];
  const float* W4=(const float*)d_in[7];  const float* b4=(const float*)d_in[8];
  const float* W5=(const float*)d_in[9];  const float* b5=(const float*)d_in[10];
  const float* W6=(const float*)d_in[11]; const float* b6=(const float*)d_in[12];
  const float* W7=(const float*)d_in[13]; const float* b7=(const float*)d_in[14];
  const float* W8=(const float*)d_in[15]; const float* b8=(const float*)d_in[16];
  float* out=(float*)d_out;

  cudaFuncSetAttribute(lstm_rec, cudaFuncAttributeMaxDynamicSharedMemorySize, 34816*4);

  zero_flags<<<1,512>>>();
  dim3 grid(64,256);
  xg_gemm<<<grid,256>>>(x, W1,W3,W5,W7, b1,b3,b5,b7, b2,b4,b6,b8);
  lstm_rec<<<128,256,34816*4>>>(W2,W4,W6,W8, out);
}

// round 7
// speedup vs baseline: 1.0174x; 1.0174x over previous
#include <cuda_runtime.h>
#include <cstdint>

#define SQ 512
#define NB 64
#define NH 1024
#define NI 256
#define NG 4096
#define HSEQ ((size_t)SQ*NB*NH)

// scratch (no allocations allowed): xg = x@Wx + bx + bh, and per-step sync flags
__device__ float g_xg[(size_t)SQ*NB*NG];
__device__ int g_flags[SQ];

__device__ __forceinline__ unsigned tf32u(float x){
  unsigned u; asm("cvt.rna.tf32.f32 %0, %1;" : "=r"(u) : "f"(x)); return u;
}
__device__ __forceinline__ float tf32f(float x){ return __uint_as_float(tf32u(x)); }
__device__ __forceinline__ void mma8(float d[4], unsigned a0,unsigned a1,unsigned a2,unsigned a3,
                                     unsigned b0,unsigned b1){
  asm("mma.sync.aligned.m16n8k8.row.col.f32.tf32.tf32.f32 "
      "{%0,%1,%2,%3},{%4,%5,%6,%7},{%8,%9},{%0,%1,%2,%3};"
      : "+f"(d[0]),"+f"(d[1]),"+f"(d[2]),"+f"(d[3])
      : "r"(a0),"r"(a1),"r"(a2),"r"(a3),"r"(b0),"r"(b1));
}
__device__ __forceinline__ void mma8f(float d[4], float4 A, float b0, float b1){
  mma8(d, __float_as_uint(A.x),__float_as_uint(A.y),__float_as_uint(A.z),__float_as_uint(A.w),
       __float_as_uint(b0), __float_as_uint(b1));
}
__device__ __forceinline__ float sigf(float x){ return 1.f/(1.f+__expf(-x)); }

// ---------------------------------------------------------------------------
// Phase 1: xg[m][gate*1024+j] = x[m,:] @ Wgate[:, j] + bx + bh
// CTA tile 128(M) x 64(N), K=256 in 8 chunks of 32. 8 warps = 4(m) x 2(n).
// Block (0,0) also re-zeroes the recurrence sync flags (stream-ordered before
// lstm_rec of the same kernel_launch call -> graph-replay deterministic).
// ---------------------------------------------------------------------------
__global__ void __launch_bounds__(256) xg_gemm(
    const float* __restrict__ x,
    const float* __restrict__ Wa,const float* __restrict__ Wb,
    const float* __restrict__ Wc,const float* __restrict__ Wd,
    const float* __restrict__ xa,const float* __restrict__ xb,
    const float* __restrict__ xc,const float* __restrict__ xd,
    const float* __restrict__ ha,const float* __restrict__ hb,
    const float* __restrict__ hc,const float* __restrict__ hd)
{
  __shared__ float As[128*36];
  __shared__ float Bs[32*72];
  __shared__ float bias[64];
  const int tid=threadIdx.x, w=tid>>5, lane=tid&31;
  const int g=lane>>2, tg=lane&3, wm=w>>1, wn=w&1;
  const int mbase=blockIdx.y*128, nb=blockIdx.x*64;
  const int gate=nb>>10, colbase=nb&1023;

  if (blockIdx.x==0 && blockIdx.y==0){           // flag reset for lstm_rec
    g_flags[tid]=0; g_flags[tid+256]=0;
  }

  const float* Wg = gate==0?Wa:gate==1?Wb:gate==2?Wc:Wd;
  const float* bx = gate==0?xa:gate==1?xb:gate==2?xc:xd;
  const float* bh = gate==0?ha:gate==1?hb:gate==2?hc:hd;
  if (tid<64) bias[tid]=bx[colbase+tid]+bh[colbase+tid];

  float acc[2][4][4];
  #pragma unroll
  for(int i=0;i<2;i++)
    #pragma unroll
    for(int j=0;j<4;j++)
      #pragma unroll
      for(int e=0;e<4;e++) acc[i][j][e]=0.f;

  for(int kc=0;kc<8;kc++){
    #pragma unroll
    for(int p=0;p<4;p++){
      int fid=tid+p*256, row=fid>>3, c4=(fid&7)*4;
      float4 v=*(const float4*)(x+(size_t)(mbase+row)*NI+kc*32+c4);
      v.x=tf32f(v.x); v.y=tf32f(v.y); v.z=tf32f(v.z); v.w=tf32f(v.w);
      *(float4*)(As+row*36+c4)=v;
    }
    #pragma unroll
    for(int p=0;p<2;p++){
      int fid=tid+p*256, r=fid>>4, c4=(fid&15)*4;
      float4 v=*(const float4*)(Wg+(size_t)(kc*32+r)*NH+colbase+c4);
      v.x=tf32f(v.x); v.y=tf32f(v.y); v.z=tf32f(v.z); v.w=tf32f(v.w);
      *(float4*)(Bs+r*72+c4)=v;
    }
    __syncthreads();
    #pragma unroll
    for(int kk=0;kk<4;kk++){
      unsigned a[2][4];
      #pragma unroll
      for(int mt=0;mt<2;mt++){
        int ar=wm*32+mt*16+g, k0=kk*8+tg;
        a[mt][0]=__float_as_uint(As[ar*36+k0]);
        a[mt][1]=__float_as_uint(As[(ar+8)*36+k0]);
        a[mt][2]=__float_as_uint(As[ar*36+k0+4]);
        a[mt][3]=__float_as_uint(As[(ar+8)*36+k0+4]);
      }
      #pragma unroll
      for(int nt=0;nt<4;nt++){
        int nc=wn*32+nt*8+g, k0=kk*8+tg;
        unsigned b0=__float_as_uint(Bs[k0*72+nc]);
        unsigned b1=__float_as_uint(Bs[(k0+4)*72+nc]);
        mma8(acc[0][nt],a[0][0],a[0][1],a[0][2],a[0][3],b0,b1);
        mma8(acc[1][nt],a[1][0],a[1][1],a[1][2],a[1][3],b0,b1);
      }
    }
    __syncthreads();
  }
  #pragma unroll
  for(int mt=0;mt<2;mt++){
    #pragma unroll
    for(int nt=0;nt<4;nt++){
      int row0=mbase+wm*32+mt*16+g;
      int colL=wn*32+nt*8+2*tg;
      float b0v=bias[colL], b1v=bias[colL+1];
      float* o0=g_xg+(size_t)row0*NG+nb+colL;
      *(float2*)o0               = make_float2(acc[mt][nt][0]+b0v, acc[mt][nt][1]+b1v);
      *(float2*)(o0+(size_t)8*NG)= make_float2(acc[mt][nt][2]+b0v, acc[mt][nt][3]+b1v);
    }
  }
}

// ---------------------------------------------------------------------------
// Phase 2: persistent recurrence, 128 CTAs (1/SM), CTA c owns h-cols [8c,8c+8)
// and the matching 8 cols of all 4 gates (N=32). tf32 m16n8k8 MMA.
//  - Wh slice pre-packed into B-fragment order in smem (Bp, 128KB).
//  - h staged per step through smem (Ah, 32KB, 1/8-K stages) with coalesced
//    LDG.128 and an XOR-swizzled packed A-frag layout: both the STS.32 scatter
//    and the LDS.128 frag reads are bank-conflict-free.
//  - warp w computes the FULL 64x32 tile over k-slab w (chunks 16q+2w,+1):
//    A and B each read from smem exactly once per chunk (no duplication).
//  - 8-way kh reduction via red (64KB), gate exchange via xch (4KB, aliases Ah),
//    gate math + c-state in registers of warps 0..3.
//  - software pipeline: stage q+1 LDG held in regs during MMA of stage q.
//  - grid-wide step sync via g_flags arrival counters (reset by xg_gemm).
// ---------------------------------------------------------------------------
__global__ void __launch_bounds__(256,1) lstm_rec(
    const float* __restrict__ Wh1,const float* __restrict__ Wh2,
    const float* __restrict__ Wh3,const float* __restrict__ Wh4,
    float* __restrict__ out)
{
  extern __shared__ float sm[];
  float* Bp  = sm;               // 32768 words (128KB): packed B frags
  float* Ah  = sm + 32768;       // 8192 words  (32KB): staged A frags (1 stage)
  float* xch = sm + 32768;       // 1024 words, aliases Ah (dead at exchange)
  float* red = sm + 40960;       // 16384 words (64KB): kh partial sums

  const int tid=threadIdx.x, w=tid>>5, lane=tid&31;
  const int g=lane>>2, tg=lane&3, cta=blockIdx.x;
  const int mtE=w&3, ntp=w>>2;   // epilogue slice

  { // one-time B pack (validated in R6): Bp[idx], idx=(s*2+p)*128 + ln*4 + e
    const float* Whs[4]={Wh1,Wh2,Wh3,Wh4};
    for(int idx=tid; idx<32768; idx+=256){
      int e=idx&3, ln=(idx>>2)&31, p=(idx>>7)&1, s=idx>>8;
      int nt=2*p+(e>>1);
      int k=8*s+(ln&3)+4*(e&1);
      Bp[idx]=tf32f(Whs[nt][(size_t)k*NH+8*cta+(ln>>2)]);
    }
  }

  // staging lane constants: row-half a_, e-bit p_, swizzle key sp=s'&7
  const int a_  = lane>>4;
  const int p_  = lane&1;
  const int sp  = (lane&15)>>1;
  const int eb  = 2*p_ + a_;
  const int sxh = sp&4, sxl = sp&3;
  int offt[4];
  #pragma unroll
  for(int j=0;j<4;j++) offt[j]=4*(j^sxl);

  __syncthreads();

  float cst[4]={0,0,0,0}, hv[4]={0,0,0,0};

  #pragma unroll 1
  for(int t=0;t<SQ;t++){
    // xg prefetch (independent of h -> hides DRAM latency across the step)
    float2 xr[8];
    if(w<4){
      const float* xb = g_xg + ((size_t)t*NB + 16*w + g)*NG + 8*cta + 2*tg;
      #pragma unroll
      for(int nt=0;nt<4;nt++){
        xr[nt]   = *(const float2*)(xb + nt*NH);
        xr[4+nt] = *(const float2*)(xb + (size_t)8*NG + nt*NH);
      }
    }

    float acc[4][4][4];
    #pragma unroll
    for(int m=0;m<4;m++)
      #pragma unroll
      for(int n=0;n<4;n++)
        #pragma unroll
        for(int e=0;e<4;e++) acc[m][n][e]=0.f;

    if(t>0){
      if(tid==0){ volatile int* f=&g_flags[t-1]; while(*f!=128) __nanosleep(32); }
      __syncthreads();
      __threadfence();   // acquire: order h loads after flag observe
      const float* hb = out + (size_t)(t-1)*NB*NH;

      float4 v[8];
      #pragma unroll
      for(int it=0;it<8;it++){            // preload stage 0 (coalesced LDG.128)
        int grp=w*8+it, rp=grp>>1, cb=grp&1;
        int row=(rp&7)+16*(rp>>3)+8*a_;
        int kl4=cb*16+(lane&15);
        v[it]=*(const float4*)(hb+(size_t)row*NH+4*kl4);
      }
      #pragma unroll 1
      for(int q=0;q<8;q++){
        __syncthreads();                  // Ah consumers of stage q-1 done
        #pragma unroll
        for(int it=0;it<8;it++){          // scatter into swizzled A-frag layout
          int grp=w*8+it, rp=grp>>1, cb=grp&1;
          int g_=rp&7, mt=rp>>3;
          int base=((cb*8+sp)*4+mt)*128 + 4*((g_<<2)^sxh) + eb;
          Ah[base+offt[0]]=tf32f(v[it].x);
          Ah[base+offt[1]]=tf32f(v[it].y);
          Ah[base+offt[2]]=tf32f(v[it].z);
          Ah[base+offt[3]]=tf32f(v[it].w);
        }
        __syncthreads();                  // Ah ready
        if(q<7){
          #pragma unroll
          for(int it=0;it<8;it++){        // LDG of q+1 overlaps MMA of q
            int grp=w*8+it, rp=grp>>1, cb=grp&1;
            int row=(rp&7)+16*(rp>>3)+8*a_;
            int kl4=cb*16+(lane&15);
            v[it]=*(const float4*)(hb+(size_t)row*NH+(q+1)*128+4*kl4);
          }
        }
        #pragma unroll
        for(int c=0;c<2;c++){             // warp w's 2 chunks in this stage
          int sl=2*w+c, key=sl&7, sg=q*16+sl;
          float4 A0=*(const float4*)(Ah+(sl*4+0)*128+4*(lane^key));
          float4 A1=*(const float4*)(Ah+(sl*4+1)*128+4*(lane^key));
          float4 A2=*(const float4*)(Ah+(sl*4+2)*128+4*(lane^key));
          float4 A3=*(const float4*)(Ah+(sl*4+3)*128+4*(lane^key));
          float4 B0=*(const float4*)(Bp+((sg*2+0)*32+lane)*4);
          float4 B1=*(const float4*)(Bp+((sg*2+1)*32+lane)*4);
          mma8f(acc[0][0],A0,B0.x,B0.y); mma8f(acc[0][1],A0,B0.z,B0.w);
          mma8f(acc[0][2],A0,B1.x,B1.y); mma8f(acc[0][3],A0,B1.z,B1.w);
          mma8f(acc[1][0],A1,B0.x,B0.y); mma8f(acc[1][1],A1,B0.z,B0.w);
          mma8f(acc[1][2],A1,B1.x,B1.y); mma8f(acc[1][3],A1,B1.z,B1.w);
          mma8f(acc[2][0],A2,B0.x,B0.y); mma8f(acc[2][1],A2,B0.z,B0.w);
          mma8f(acc[2][2],A2,B1.x,B1.y); mma8f(acc[2][3],A2,B1.z,B1.w);
          mma8f(acc[3][0],A3,B0.x,B0.y); mma8f(acc[3][1],A3,B0.z,B0.w);
          mma8f(acc[3][2],A3,B1.x,B1.y); mma8f(acc[3][3],A3,B1.z,B1.w);
        }
      }
    }
    __syncthreads();
    #pragma unroll
    for(int m=0;m<4;m++)                  // kh partial -> red[w]
      #pragma unroll
      for(int n=0;n<4;n++)
        *(float4*)(red+((w*16+m*4+n)*32+lane)*4) =
          make_float4(acc[m][n][0],acc[m][n][1],acc[m][n][2],acc[m][n][3]);
    __syncthreads();
    float s0[4]={0,0,0,0}, s1[4]={0,0,0,0};
    #pragma unroll
    for(int kh=0;kh<8;kh++){              // sum 8 kh slabs for slice (mtE,ntp)
      float4 u0=*(const float4*)(red+((kh*16+mtE*4+ntp*2+0)*32+lane)*4);
      float4 u1=*(const float4*)(red+((kh*16+mtE*4+ntp*2+1)*32+lane)*4);
      s0[0]+=u0.x; s0[1]+=u0.y; s0[2]+=u0.z; s0[3]+=u0.w;
      s1[0]+=u1.x; s1[1]+=u1.y; s1[2]+=u1.z; s1[3]+=u1.w;
    }
    if(w>=4){                             // gates o,cand -> exchange
      *(float4*)(xch+((mtE*2+0)*32+lane)*4)=make_float4(s0[0],s0[1],s0[2],s0[3]);
      *(float4*)(xch+((mtE*2+1)*32+lane)*4)=make_float4(s1[0],s1[1],s1[2],s1[3]);
    }
    __syncthreads();
    if(w<4){
      float4 x2=*(const float4*)(xch+((w*2+0)*32+lane)*4);   // gate o
      float4 x3=*(const float4*)(xch+((w*2+1)*32+lane)*4);   // gate cand
      float fg[4],ig[4],og[4],cg[4];
      fg[0]=s0[0]+xr[0].x; fg[1]=s0[1]+xr[0].y; fg[2]=s0[2]+xr[4].x; fg[3]=s0[3]+xr[4].y;
      ig[0]=s1[0]+xr[1].x; ig[1]=s1[1]+xr[1].y; ig[2]=s1[2]+xr[5].x; ig[3]=s1[3]+xr[5].y;
      og[0]=x2.x+xr[2].x;  og[1]=x2.y+xr[2].y;  og[2]=x2.z+xr[6].x;  og[3]=x2.w+xr[6].y;
      cg[0]=x3.x+xr[3].x;  cg[1]=x3.y+xr[3].y;  cg[2]=x3.z+xr[7].x;  cg[3]=x3.w+xr[7].y;
      #pragma unroll
      for(int e=0;e<4;e++){
        float f=sigf(fg[e]), ii=sigf(ig[e]), o=sigf(og[e]), cd=tanhf(cg[e]);
        cst[e]=f*cst[e]+ii*cd;
        hv[e]=o*tanhf(cst[e]);
      }
      float* hw = out + ((size_t)t*NB + 16*w + g)*NH + 8*cta + 2*tg;
      *(float2*)hw                = make_float2(hv[0],hv[1]);
      *(float2*)(hw+(size_t)8*NH) = make_float2(hv[2],hv[3]);
    }
    __threadfence();   // release: h_seq[t] visible before flag arrival
    __syncthreads();
    if(tid==0) atomicAdd(&g_flags[t],1);
  }

  if(w<4){  // tails: h_final (== h_seq[511]) then c_final
    float* ho = out + HSEQ + (size_t)(16*w+g)*NH + 8*cta + 2*tg;
    float* co = ho + (size_t)NB*NH;
    *(float2*)ho                = make_float2(hv[0],hv[1]);
    *(float2*)(ho+(size_t)8*NH) = make_float2(hv[2],hv[3]);
    *(float2*)co                = make_float2(cst[0],cst[1]);
    *(float2*)(co+(size_t)8*NH) = make_float2(cst[2],cst[3]);
  }
}

extern "C" void kernel_launch(void* const* d_in, const int* in_sizes, int n_in,
                              void* d_out, int out_size){
  const float* x =(const float*)d_in[0];
  const float* W1=(const float*)d_in[1];  const float* b1=(const float*)d_in[2];
  const float* W2=(const float*)d_in[3];  const float* b2=(const float*)d_in[4];
  const float* W3=(const float*)d_in[5];  const float* b3=(const float*)d_in[6];
  const float* W4=(const float*)d_in[7];  const float* b4=(const float*)d_in[8];
  const float* W5=(const float*)d_in[9];  const float* b5=(const float*)d_in[10];
  const float* W6=(const float*)d_in[11]; const float* b6=(const float*)d_in[12];
  const float* W7=(const float*)d_in[13]; const float* b7=(const float*)d_in[14];
  const float* W8=(const float*)d_in[15]; const float* b8=(const float*)d_in[16];
  float* out=(float*)d_out;

  cudaFuncSetAttribute(lstm_rec, cudaFuncAttributeMaxDynamicSharedMemorySize, 229376);

  dim3 grid(64,256);
  xg_gemm<<<grid,256>>>(x, W1,W3,W5,W7, b1,b3,b5,b7, b2,b4,b6,b8);
  lstm_rec<<<128,256,229376>>>(W2,W4,W6,W8, out);
}

// round 9
// speedup vs baseline: 1.4172x; 1.3930x over previous
#include <cuda_runtime.h>
#include <cstdint>

#define SQ 512
#define NB 64
#define NH 1024
#define NI 256
#define NG 4096
#define HSEQ ((size_t)SQ*NB*NH)

// scratch (no allocations allowed): xg = x@Wx + bx + bh, and per-step sync flags
__device__ float g_xg[(size_t)SQ*NB*NG];
__device__ int g_flags[SQ];

__device__ __forceinline__ unsigned tf32u(float x){
  unsigned u; asm("cvt.rna.tf32.f32 %0, %1;" : "=r"(u) : "f"(x)); return u;
}
__device__ __forceinline__ float tf32f(float x){ return __uint_as_float(tf32u(x)); }
__device__ __forceinline__ void mma8(float d[4], unsigned a0,unsigned a1,unsigned a2,unsigned a3,
                                     unsigned b0,unsigned b1){
  asm("mma.sync.aligned.m16n8k8.row.col.f32.tf32.tf32.f32 "
      "{%0,%1,%2,%3},{%4,%5,%6,%7},{%8,%9},{%0,%1,%2,%3};"
      : "+f"(d[0]),"+f"(d[1]),"+f"(d[2]),"+f"(d[3])
      : "r"(a0),"r"(a1),"r"(a2),"r"(a3),"r"(b0),"r"(b1));
}
__device__ __forceinline__ void mma8f(float d[4], float4 A, float b0, float b1){
  mma8(d, __float_as_uint(A.x),__float_as_uint(A.y),__float_as_uint(A.z),__float_as_uint(A.w),
       __float_as_uint(b0), __float_as_uint(b1));
}
__device__ __forceinline__ float sigf(float x){ return 1.f/(1.f+__expf(-x)); }

// ---------------------------------------------------------------------------
// Phase 1: xg[m][gate*1024+j] = x[m,:] @ Wgate[:, j] + bx + bh
// CTA tile 128(M) x 64(N), K=256 in 8 chunks of 32. 8 warps = 4(m) x 2(n).
// Block (0,0) also re-zeroes the recurrence sync flags (stream-ordered before
// lstm_rec of the same kernel_launch call -> graph-replay deterministic).
// ---------------------------------------------------------------------------
__global__ void __launch_bounds__(256) xg_gemm(
    const float* __restrict__ x,
    const float* __restrict__ Wa,const float* __restrict__ Wb,
    const float* __restrict__ Wc,const float* __restrict__ Wd,
    const float* __restrict__ xa,const float* __restrict__ xb,
    const float* __restrict__ xc,const float* __restrict__ xd,
    const float* __restrict__ ha,const float* __restrict__ hb,
    const float* __restrict__ hc,const float* __restrict__ hd)
{
  __shared__ float As[128*36];
  __shared__ float Bs[32*72];
  __shared__ float bias[64];
  const int tid=threadIdx.x, w=tid>>5, lane=tid&31;
  const int g=lane>>2, tg=lane&3, wm=w>>1, wn=w&1;
  const int mbase=blockIdx.y*128, nb=blockIdx.x*64;
  const int gate=nb>>10, colbase=nb&1023;

  if (blockIdx.x==0 && blockIdx.y==0){           // flag reset for lstm_rec
    g_flags[tid]=0; g_flags[tid+256]=0;
  }

  const float* Wg = gate==0?Wa:gate==1?Wb:gate==2?Wc:Wd;
  const float* bx = gate==0?xa:gate==1?xb:gate==2?xc:xd;
  const float* bh = gate==0?ha:gate==1?hb:gate==2?hc:hd;
  if (tid<64) bias[tid]=bx[colbase+tid]+bh[colbase+tid];

  float acc[2][4][4];
  #pragma unroll
  for(int i=0;i<2;i++)
    #pragma unroll
    for(int j=0;j<4;j++)
      #pragma unroll
      for(int e=0;e<4;e++) acc[i][j][e]=0.f;

  for(int kc=0;kc<8;kc++){
    #pragma unroll
    for(int p=0;p<4;p++){
      int fid=tid+p*256, row=fid>>3, c4=(fid&7)*4;
      float4 v=*(const float4*)(x+(size_t)(mbase+row)*NI+kc*32+c4);
      v.x=tf32f(v.x); v.y=tf32f(v.y); v.z=tf32f(v.z); v.w=tf32f(v.w);
      *(float4*)(As+row*36+c4)=v;
    }
    #pragma unroll
    for(int p=0;p<2;p++){
      int fid=tid+p*256, r=fid>>4, c4=(fid&15)*4;
      float4 v=*(const float4*)(Wg+(size_t)(kc*32+r)*NH+colbase+c4);
      v.x=tf32f(v.x); v.y=tf32f(v.y); v.z=tf32f(v.z); v.w=tf32f(v.w);
      *(float4*)(Bs+r*72+c4)=v;
    }
    __syncthreads();
    #pragma unroll
    for(int kk=0;kk<4;kk++){
      unsigned a[2][4];
      #pragma unroll
      for(int mt=0;mt<2;mt++){
        int ar=wm*32+mt*16+g, k0=kk*8+tg;
        a[mt][0]=__float_as_uint(As[ar*36+k0]);
        a[mt][1]=__float_as_uint(As[(ar+8)*36+k0]);
        a[mt][2]=__float_as_uint(As[ar*36+k0+4]);
        a[mt][3]=__float_as_uint(As[(ar+8)*36+k0+4]);
      }
      #pragma unroll
      for(int nt=0;nt<4;nt++){
        int nc=wn*32+nt*8+g, k0=kk*8+tg;
        unsigned b0=__float_as_uint(Bs[k0*72+nc]);
        unsigned b1=__float_as_uint(Bs[(k0+4)*72+nc]);
        mma8(acc[0][nt],a[0][0],a[0][1],a[0][2],a[0][3],b0,b1);
        mma8(acc[1][nt],a[1][0],a[1][1],a[1][2],a[1][3],b0,b1);
      }
    }
    __syncthreads();
  }
  #pragma unroll
  for(int mt=0;mt<2;mt++){
    #pragma unroll
    for(int nt=0;nt<4;nt++){
      int row0=mbase+wm*32+mt*16+g;
      int colL=wn*32+nt*8+2*tg;
      float b0v=bias[colL], b1v=bias[colL+1];
      float* o0=g_xg+(size_t)row0*NG+nb+colL;
      *(float2*)o0               = make_float2(acc[mt][nt][0]+b0v, acc[mt][nt][1]+b1v);
      *(float2*)(o0+(size_t)8*NG)= make_float2(acc[mt][nt][2]+b0v, acc[mt][nt][3]+b1v);
    }
  }
}

// ---------------------------------------------------------------------------
// Phase 2: persistent recurrence, 128 CTAs (1/SM), 512 threads (16 warps).
// CTA c owns h-cols [8c,8c+8) and the matching 8 cols of all 4 gates (N=32).
//  - Wh slice pre-packed into B-fragment order in smem (Bp, 128KB).
//  - h staged per step through smem (Ah, 32KB, 1/8-K stages) with coalesced
//    LDG.128 and an XOR-swizzled packed A-frag layout (conflict-free STS+LDS).
//  - warp w computes the FULL 64x32 tile over k-slab w (chunk w of each of
//    8 stages): 128 MMA/warp/step, A and B each read from smem exactly once.
//  - 16-way kh reduction: warps 8-15 write red, warps 0-7 add in place,
//    then 8-slot sum epilogue; gate exchange via xch (aliases Ah).
//  - grid-wide step sync via g_flags arrival counters (reset by xg_gemm);
//    wait uses (<128) so stale flags never hang (ncu replay safe).
// ---------------------------------------------------------------------------
__global__ void __launch_bounds__(512,1) lstm_rec(
    const float* __restrict__ Wh1,const float* __restrict__ Wh2,
    const float* __restrict__ Wh3,const float* __restrict__ Wh4,
    float* __restrict__ out)
{
  extern __shared__ float sm[];
  float* Bp  = sm;               // 32768 words (128KB): packed B frags
  float* Ah  = sm + 32768;       // 8192 words  (32KB): staged A frags (1 stage)
  float* xch = sm + 32768;       // 1024 words, aliases Ah (dead at exchange)
  float* red = sm + 40960;       // 16384 words (64KB): kh partial sums (8 slots)

  const int tid=threadIdx.x, w=tid>>5, lane=tid&31;
  const int g=lane>>2, tg=lane&3, cta=blockIdx.x;
  const int mtE=w&3, ntp=(w>>2)&1;   // epilogue slice (w<8)

  { // one-time B pack: Bp[idx], idx=(s*2+p)*128 + ln*4 + e
    const float* Whs[4]={Wh1,Wh2,Wh3,Wh4};
    for(int idx=tid; idx<32768; idx+=512){
      int e=idx&3, ln=(idx>>2)&31, p=(idx>>7)&1, s=idx>>8;
      int nt=2*p+(e>>1);
      int k=8*s+(ln&3)+4*(e&1);
      Bp[idx]=tf32f(Whs[nt][(size_t)k*NH+8*cta+(ln>>2)]);
    }
  }

  // staging lane constants: row-half a_, e-bit p_, swizzle key sp
  const int a_  = lane>>4;
  const int p_  = lane&1;
  const int sp  = (lane&15)>>1;
  const int eb  = 2*p_ + a_;
  const int sxh = sp&4, sxl = sp&3;
  int offt[4];
  #pragma unroll
  for(int j=0;j<4;j++) offt[j]=4*(j^sxl);

  __syncthreads();

  float cst[4]={0,0,0,0}, hv[4]={0,0,0,0};

  #pragma unroll 1
  for(int t=0;t<SQ;t++){
    float acc[4][4][4];
    #pragma unroll
    for(int m=0;m<4;m++)
      #pragma unroll
      for(int n=0;n<4;n++)
        #pragma unroll
        for(int e=0;e<4;e++) acc[m][n][e]=0.f;

    if(t>0){
      if(tid==0){ volatile int* f=&g_flags[t-1];
                  while(((unsigned)*f)<128u) __nanosleep(32); }
      __syncthreads();                    // all threads see release (h in L2; L1 cold)
      const float* hb = out + (size_t)(t-1)*NB*NH;

      float4 v[4];
      #pragma unroll
      for(int it=0;it<4;it++){            // preload stage 0 (coalesced LDG.128)
        int grp=w*4+it, rp=grp>>1, cb=grp&1;
        int row=(rp&7)+16*(rp>>3)+8*a_;
        int kl4=cb*16+(lane&15);
        v[it]=*(const float4*)(hb+(size_t)row*NH+4*kl4);
      }
      #pragma unroll 1
      for(int q=0;q<8;q++){
        __syncthreads();                  // Ah consumers of stage q-1 done
        #pragma unroll
        for(int it=0;it<4;it++){          // scatter into swizzled A-frag layout
          int grp=w*4+it, rp=grp>>1, cb=grp&1;
          int g_=rp&7, mt=rp>>3;
          int base=((cb*8+sp)*4+mt)*128 + 4*((g_<<2)^sxh) + eb;
          Ah[base+offt[0]]=tf32f(v[it].x);
          Ah[base+offt[1]]=tf32f(v[it].y);
          Ah[base+offt[2]]=tf32f(v[it].z);
          Ah[base+offt[3]]=tf32f(v[it].w);
        }
        __syncthreads();                  // Ah ready
        if(q<7){
          #pragma unroll
          for(int it=0;it<4;it++){        // LDG of q+1 overlaps MMA of q
            int grp=w*4+it, rp=grp>>1, cb=grp&1;
            int row=(rp&7)+16*(rp>>3)+8*a_;
            int kl4=cb*16+(lane&15);
            v[it]=*(const float4*)(hb+(size_t)row*NH+(q+1)*128+4*kl4);
          }
        }
        {                                 // warp w's chunk in this stage
          int sl=w, key=sl&7, sg=q*16+sl;
          float4 A0=*(const float4*)(Ah+(sl*4+0)*128+4*(lane^key));
          float4 A1=*(const float4*)(Ah+(sl*4+1)*128+4*(lane^key));
          float4 A2=*(const float4*)(Ah+(sl*4+2)*128+4*(lane^key));
          float4 A3=*(const float4*)(Ah+(sl*4+3)*128+4*(lane^key));
          float4 B0=*(const float4*)(Bp+((sg*2+0)*32+lane)*4);
          float4 B1=*(const float4*)(Bp+((sg*2+1)*32+lane)*4);
          mma8f(acc[0][0],A0,B0.x,B0.y); mma8f(acc[0][1],A0,B0.z,B0.w);
          mma8f(acc[0][2],A0,B1.x,B1.y); mma8f(acc[0][3],A0,B1.z,B1.w);
          mma8f(acc[1][0],A1,B0.x,B0.y); mma8f(acc[1][1],A1,B0.z,B0.w);
          mma8f(acc[1][2],A1,B1.x,B1.y); mma8f(acc[1][3],A1,B1.z,B1.w);
          mma8f(acc[2][0],A2,B0.x,B0.y); mma8f(acc[2][1],A2,B0.z,B0.w);
          mma8f(acc[2][2],A2,B1.x,B1.y); mma8f(acc[2][3],A2,B1.z,B1.w);
          mma8f(acc[3][0],A3,B0.x,B0.y); mma8f(acc[3][1],A3,B0.z,B0.w);
          mma8f(acc[3][2],A3,B1.x,B1.y); mma8f(acc[3][3],A3,B1.z,B1.w);
        }
      }
    }
    // xg loads issue here; latency hidden by the reduction barriers below
    float2 xr[8];
    if(w<4){
      const float* xb = g_xg + ((size_t)t*NB + 16*w + g)*NG + 8*cta + 2*tg;
      #pragma unroll
      for(int nt=0;nt<4;nt++){
        xr[nt]   = *(const float2*)(xb + nt*NH);
        xr[4+nt] = *(const float2*)(xb + (size_t)8*NG + nt*NH);
      }
    }
    __syncthreads();
    if(w>=8){                             // phase A: slabs 8..15 -> red
      int slot=w-8;
      #pragma unroll
      for(int m=0;m<4;m++)
        #pragma unroll
        for(int n=0;n<4;n++)
          *(float4*)(red+((slot*16+m*4+n)*32+lane)*4) =
            make_float4(acc[m][n][0],acc[m][n][1],acc[m][n][2],acc[m][n][3]);
    }
    __syncthreads();
    if(w<8){                              // phase B: red[w] += slab w (in place)
      #pragma unroll
      for(int m=0;m<4;m++)
        #pragma unroll
        for(int n=0;n<4;n++){
          float4 u=*(const float4*)(red+((w*16+m*4+n)*32+lane)*4);
          u.x+=acc[m][n][0]; u.y+=acc[m][n][1]; u.z+=acc[m][n][2]; u.w+=acc[m][n][3];
          *(float4*)(red+((w*16+m*4+n)*32+lane)*4)=u;
        }
    }
    __syncthreads();
    float s0[4]={0,0,0,0}, s1[4]={0,0,0,0};
    if(w<8){                              // phase C: sum 8 slots for slice (mtE,ntp)
      #pragma unroll
      for(int kh=0;kh<8;kh++){
        float4 u0=*(const float4*)(red+((kh*16+mtE*4+ntp*2+0)*32+lane)*4);
        float4 u1=*(const float4*)(red+((kh*16+mtE*4+ntp*2+1)*32+lane)*4);
        s0[0]+=u0.x; s0[1]+=u0.y; s0[2]+=u0.z; s0[3]+=u0.w;
        s1[0]+=u1.x; s1[1]+=u1.y; s1[2]+=u1.z; s1[3]+=u1.w;
      }
      if(w>=4){                           // gates o,cand -> exchange
        *(float4*)(xch+((mtE*2+0)*32+lane)*4)=make_float4(s0[0],s0[1],s0[2],s0[3]);
        *(float4*)(xch+((mtE*2+1)*32+lane)*4)=make_float4(s1[0],s1[1],s1[2],s1[3]);
      }
    }
    __syncthreads();
    if(w<4){
      float4 x2=*(const float4*)(xch+((w*2+0)*32+lane)*4);   // gate o
      float4 x3=*(const float4*)(xch+((w*2+1)*32+lane)*4);   // gate cand
      float fg[4],ig[4],og[4],cg[4];
      fg[0]=s0[0]+xr[0].x; fg[1]=s0[1]+xr[0].y; fg[2]=s0[2]+xr[4].x; fg[3]=s0[3]+xr[4].y;
      ig[0]=s1[0]+xr[1].x; ig[1]=s1[1]+xr[1].y; ig[2]=s1[2]+xr[5].x; ig[3]=s1[3]+xr[5].y;
      og[0]=x2.x+xr[2].x;  og[1]=x2.y+xr[2].y;  og[2]=x2.z+xr[6].x;  og[3]=x2.w+xr[6].y;
      cg[0]=x3.x+xr[3].x;  cg[1]=x3.y+xr[3].y;  cg[2]=x3.z+xr[7].x;  cg[3]=x3.w+xr[7].y;
      #pragma unroll
      for(int e=0;e<4;e++){
        float f=sigf(fg[e]), ii=sigf(ig[e]), o=sigf(og[e]), cd=tanhf(cg[e]);
        cst[e]=f*cst[e]+ii*cd;
        hv[e]=o*tanhf(cst[e]);
      }
      float* hw = out + ((size_t)t*NB + 16*w + g)*NH + 8*cta + 2*tg;
      *(float2*)hw                = make_float2(hv[0],hv[1]);
      *(float2*)(hw+(size_t)8*NH) = make_float2(hv[2],hv[3]);
      __threadfence();                    // release: only writers fence
    }
    __syncthreads();
    if(tid==0) atomicAdd(&g_flags[t],1);
  }

  if(w<4){  // tails: h_final (== h_seq[511]) then c_final
    float* ho = out + HSEQ + (size_t)(16*w+g)*NH + 8*cta + 2*tg;
    float* co = ho + (size_t)NB*NH;
    *(float2*)ho                = make_float2(hv[0],hv[1]);
    *(float2*)(ho+(size_t)8*NH) = make_float2(hv[2],hv[3]);
    *(float2*)co                = make_float2(cst[0],cst[1]);
    *(float2*)(co+(size_t)8*NH) = make_float2(cst[2],cst[3]);
  }
}

extern "C" void kernel_launch(void* const* d_in, const int* in_sizes, int n_in,
                              void* d_out, int out_size){
  const float* x =(const float*)d_in[0];
  const float* W1=(const float*)d_in[1];  const float* b1=(const float*)d_in[2];
  const float* W2=(const float*)d_in[3];  const float* b2=(const float*)d_in[4];
  const float* W3=(const float*)d_in[5];  const float* b3=(const float*)d_in[6];
  const float* W4=(const float*)d_in[7];  const float* b4=(const float*)d_in[8];
  const float* W5=(const float*)d_in[9];  const float* b5=(const float*)d_in[10];
  const float* W6=(const float*)d_in[11]; const float* b6=(const float*)d_in[12];
  const float* W7=(const float*)d_in[13]; const float* b7=(const float*)d_in[14];
  const float* W8=(const float*)d_in[15]; const float* b8=(const float*)d_in[16];
  float* out=(float*)d_out;

  cudaFuncSetAttribute(lstm_rec, cudaFuncAttributeMaxDynamicSharedMemorySize, 229376);

  dim3 grid(64,256);
  xg_gemm<<<grid,256>>>(x, W1,W3,W5,W7, b1,b3,b5,b7, b2,b4,b6,b8);
  lstm_rec<<<128,512,229376>>>(W2,W4,W6,W8, out);
}

// round 10
// speedup vs baseline: 2.4224x; 1.7093x over previous
#include <cuda_runtime.h>
#include <cstdint>

#define SQ 512
#define NB 64
#define NH 1024
#define NI 256
#define NG 4096
#define HSEQ ((size_t)SQ*NB*NH)

// scratch (no allocations allowed)
__device__ float g_xg[(size_t)SQ*NB*NG];     // xg = x@Wx + bx + bh
__device__ float g_hfrag[(size_t)SQ*NB*NH];  // h in tf32 A-fragment order
__device__ int   g_flags[SQ];                // per-step arrival counters

__device__ __forceinline__ unsigned tf32u(float x){
  unsigned u; asm("cvt.rna.tf32.f32 %0, %1;" : "=r"(u) : "f"(x)); return u;
}
__device__ __forceinline__ float tf32f(float x){ return __uint_as_float(tf32u(x)); }
__device__ __forceinline__ void mma8(float d[4], unsigned a0,unsigned a1,unsigned a2,unsigned a3,
                                     unsigned b0,unsigned b1){
  asm("mma.sync.aligned.m16n8k8.row.col.f32.tf32.tf32.f32 "
      "{%0,%1,%2,%3},{%4,%5,%6,%7},{%8,%9},{%0,%1,%2,%3};"
      : "+f"(d[0]),"+f"(d[1]),"+f"(d[2]),"+f"(d[3])
      : "r"(a0),"r"(a1),"r"(a2),"r"(a3),"r"(b0),"r"(b1));
}
__device__ __forceinline__ void mma8f(float d[4], float4 A, float b0, float b1){
  mma8(d, __float_as_uint(A.x),__float_as_uint(A.y),__float_as_uint(A.z),__float_as_uint(A.w),
       __float_as_uint(b0), __float_as_uint(b1));
}
__device__ __forceinline__ float sigf(float x){ return 1.f/(1.f+__expf(-x)); }

// ---------------------------------------------------------------------------
// Phase 1: xg[m][gate*1024+j] = x[m,:] @ Wgate[:, j] + bx + bh
// CTA tile 128(M) x 64(N), K=256 in 8 chunks of 32. 8 warps = 4(m) x 2(n).
// Block (0,0) also re-zeroes the recurrence sync flags (stream-ordered before
// lstm_rec of the same kernel_launch call -> graph-replay deterministic).
// ---------------------------------------------------------------------------
__global__ void __launch_bounds__(256) xg_gemm(
    const float* __restrict__ x,
    const float* __restrict__ Wa,const float* __restrict__ Wb,
    const float* __restrict__ Wc,const float* __restrict__ Wd,
    const float* __restrict__ xa,const float* __restrict__ xb,
    const float* __restrict__ xc,const float* __restrict__ xd,
    const float* __restrict__ ha,const float* __restrict__ hb,
    const float* __restrict__ hc,const float* __restrict__ hd)
{
  __shared__ float As[128*36];
  __shared__ float Bs[32*72];
  __shared__ float bias[64];
  const int tid=threadIdx.x, w=tid>>5, lane=tid&31;
  const int g=lane>>2, tg=lane&3, wm=w>>1, wn=w&1;
  const int mbase=blockIdx.y*128, nb=blockIdx.x*64;
  const int gate=nb>>10, colbase=nb&1023;

  if (blockIdx.x==0 && blockIdx.y==0){           // flag reset for lstm_rec
    g_flags[tid]=0; g_flags[tid+256]=0;
  }

  const float* Wg = gate==0?Wa:gate==1?Wb:gate==2?Wc:Wd;
  const float* bx = gate==0?xa:gate==1?xb:gate==2?xc:xd;
  const float* bh = gate==0?ha:gate==1?hb:gate==2?hc:hd;
  if (tid<64) bias[tid]=bx[colbase+tid]+bh[colbase+tid];

  float acc[2][4][4];
  #pragma unroll
  for(int i=0;i<2;i++)
    #pragma unroll
    for(int j=0;j<4;j++)
      #pragma unroll
      for(int e=0;e<4;e++) acc[i][j][e]=0.f;

  for(int kc=0;kc<8;kc++){
    #pragma unroll
    for(int p=0;p<4;p++){
      int fid=tid+p*256, row=fid>>3, c4=(fid&7)*4;
      float4 v=*(const float4*)(x+(size_t)(mbase+row)*NI+kc*32+c4);
      v.x=tf32f(v.x); v.y=tf32f(v.y); v.z=tf32f(v.z); v.w=tf32f(v.w);
      *(float4*)(As+row*36+c4)=v;
    }
    #pragma unroll
    for(int p=0;p<2;p++){
      int fid=tid+p*256, r=fid>>4, c4=(fid&15)*4;
      float4 v=*(const float4*)(Wg+(size_t)(kc*32+r)*NH+colbase+c4);
      v.x=tf32f(v.x); v.y=tf32f(v.y); v.z=tf32f(v.z); v.w=tf32f(v.w);
      *(float4*)(Bs+r*72+c4)=v;
    }
    __syncthreads();
    #pragma unroll
    for(int kk=0;kk<4;kk++){
      unsigned a[2][4];
      #pragma unroll
      for(int mt=0;mt<2;mt++){
        int ar=wm*32+mt*16+g, k0=kk*8+tg;
        a[mt][0]=__float_as_uint(As[ar*36+k0]);
        a[mt][1]=__float_as_uint(As[(ar+8)*36+k0]);
        a[mt][2]=__float_as_uint(As[ar*36+k0+4]);
        a[mt][3]=__float_as_uint(As[(ar+8)*36+k0+4]);
      }
      #pragma unroll
      for(int nt=0;nt<4;nt++){
        int nc=wn*32+nt*8+g, k0=kk*8+tg;
        unsigned b0=__float_as_uint(Bs[k0*72+nc]);
        unsigned b1=__float_as_uint(Bs[(k0+4)*72+nc]);
        mma8(acc[0][nt],a[0][0],a[0][1],a[0][2],a[0][3],b0,b1);
        mma8(acc[1][nt],a[1][0],a[1][1],a[1][2],a[1][3],b0,b1);
      }
    }
    __syncthreads();
  }
  #pragma unroll
  for(int mt=0;mt<2;mt++){
    #pragma unroll
    for(int nt=0;nt<4;nt++){
      int row0=mbase+wm*32+mt*16+g;
      int colL=wn*32+nt*8+2*tg;
      float b0v=bias[colL], b1v=bias[colL+1];
      float* o0=g_xg+(size_t)row0*NG+nb+colL;
      *(float2*)o0               = make_float2(acc[mt][nt][0]+b0v, acc[mt][nt][1]+b1v);
      *(float2*)(o0+(size_t)8*NG)= make_float2(acc[mt][nt][2]+b0v, acc[mt][nt][3]+b1v);
    }
  }
}

// ---------------------------------------------------------------------------
// Phase 2: persistent recurrence, 128 CTAs (1/SM), 512 threads (16 warps).
// CTA c owns h-cols [8c,8c+8) = k-chunk c, and the matching 8 cols of all 4
// gates (N=32 = 4 gates x 1 n8 tile each).
//  - h exchanged via g_hfrag, pre-converted tf32 A-fragments: layout
//    [t][chunk(128)][mt(4)][lane(32)] float4. Producer CTA c writes chunk c
//    (in-warp shuffle transpose). Consumers LDG.128 straight into MMA
//    operands: NO smem staging, NO per-stage barriers, NO reader cvt.
//  - warp w = (mt=w>>2, kh=w&3): m-tile mt, all 4 gates, chunks 32kh..32kh+31.
//    Per chunk: 1 LDG.128 (A) + 2 LDS.128 (B frags) + 4 MMA; dual accumulators
//    (even/odd chunk) for ILP; barrier-free mainloop.
//  - 4-way kh reduction via red (24KB); gates computed in the kh==0 warps'
//    registers (no exchange needed: warp owns all 4 gates of its rows).
//  - 3 barriers/step. Grid sync via g_flags counters (reset by xg_gemm);
//    wait uses (<128) so stale flags never hang (ncu replay safe).
// ---------------------------------------------------------------------------
__global__ void __launch_bounds__(512,1) lstm_rec(
    const float* __restrict__ Wh1,const float* __restrict__ Wh2,
    const float* __restrict__ Wh3,const float* __restrict__ Wh4,
    float* __restrict__ out)
{
  extern __shared__ float sm[];
  float* Bp  = sm;               // 32768 words (128KB): packed B frags
  float* red = sm + 32768;       // 6144 words (24KB): kh partial sums (3 slots)

  const int tid=threadIdx.x, w=tid>>5, lane=tid&31;
  const int g=lane>>2, tg=lane&3, cta=blockIdx.x;
  const int mt=w>>2, kh=w&3;

  { // one-time B pack: Bp[idx], idx=(s*2+p)*128 + ln*4 + e
    const float* Whs[4]={Wh1,Wh2,Wh3,Wh4};
    for(int idx=tid; idx<32768; idx+=512){
      int e=idx&3, ln=(idx>>2)&31, p=(idx>>7)&1, s=idx>>8;
      int nt=2*p+(e>>1);
      int k=8*s+(ln&3)+4*(e&1);
      Bp[idx]=tf32f(Whs[nt][(size_t)k*NH+8*cta+(ln>>2)]);
    }
  }
  __syncthreads();

  const float4* bq = (const float4*)Bp;
  float4* red4 = (float4*)red;
  float cst[4]={0,0,0,0}, hv[4]={0,0,0,0};

  #pragma unroll 1
  for(int t=0;t<SQ;t++){
    // xg loads: independent of the flag -> issue before the wait
    float2 xr[8];
    if(kh==0){
      const float* xb = g_xg + ((size_t)t*NB + 16*mt + g)*NG + 8*cta + 2*tg;
      #pragma unroll
      for(int nt=0;nt<4;nt++){
        xr[nt]   = *(const float2*)(xb + nt*NH);             // row r0, gate nt
        xr[4+nt] = *(const float2*)(xb + (size_t)8*NG + nt*NH); // row r1
      }
    }

    float accA[4][4], accB[4][4];
    #pragma unroll
    for(int n=0;n<4;n++)
      #pragma unroll
      for(int e=0;e<4;e++){ accA[n][e]=0.f; accB[n][e]=0.f; }

    if(t>0){
      if(tid==0){ volatile int* f=&g_flags[t-1];
                  while(((unsigned)*f)<128u) __nanosleep(16); }
      __syncthreads();                    // barrier 1: flag observed
      const float4* fb = (const float4*)(g_hfrag + (size_t)(t-1)*NB*NH);
      #pragma unroll 4
      for(int cc=0; cc<32; cc+=2){
        int c0=(kh<<5)+cc;
        float4 A0 = fb[c0*128 + mt*32 + lane];
        float4 P0 = bq[(c0*2+0)*32 + lane];
        float4 Q0 = bq[(c0*2+1)*32 + lane];
        float4 A1 = fb[(c0+1)*128 + mt*32 + lane];
        float4 P1 = bq[((c0+1)*2+0)*32 + lane];
        float4 Q1 = bq[((c0+1)*2+1)*32 + lane];
        mma8f(accA[0],A0,P0.x,P0.y); mma8f(accA[1],A0,P0.z,P0.w);
        mma8f(accA[2],A0,Q0.x,Q0.y); mma8f(accA[3],A0,Q0.z,Q0.w);
        mma8f(accB[0],A1,P1.x,P1.y); mma8f(accB[1],A1,P1.z,P1.w);
        mma8f(accB[2],A1,Q1.x,Q1.y); mma8f(accB[3],A1,Q1.z,Q1.w);
      }
    }
    #pragma unroll
    for(int n=0;n<4;n++)
      #pragma unroll
      for(int e=0;e<4;e++) accA[n][e]+=accB[n][e];

    if(kh>0){                             // phase A: slabs kh=1..3 -> red
      #pragma unroll
      for(int n=0;n<4;n++)
        red4[(((kh-1)*4+mt)*4+n)*32+lane] =
          make_float4(accA[n][0],accA[n][1],accA[n][2],accA[n][3]);
    }
    __syncthreads();                      // barrier 2: red ready
    if(kh==0){
      #pragma unroll
      for(int s=0;s<3;s++)
        #pragma unroll
        for(int n=0;n<4;n++){
          float4 u=red4[((s*4+mt)*4+n)*32+lane];
          accA[n][0]+=u.x; accA[n][1]+=u.y; accA[n][2]+=u.z; accA[n][3]+=u.w;
        }
      // gates: nt order = f,i,o,cand; element e: 0=(r0,c0) 1=(r0,c1) 2=(r1,c0) 3=(r1,c1)
      float gv[4][4];
      #pragma unroll
      for(int n=0;n<4;n++){
        gv[n][0]=accA[n][0]+xr[n].x;   gv[n][1]=accA[n][1]+xr[n].y;
        gv[n][2]=accA[n][2]+xr[4+n].x; gv[n][3]=accA[n][3]+xr[4+n].y;
      }
      #pragma unroll
      for(int e=0;e<4;e++){
        float f=sigf(gv[0][e]), ii=sigf(gv[1][e]);
        float o=sigf(gv[2][e]), cd=tanhf(gv[3][e]);
        cst[e]=f*cst[e]+ii*cd;
        hv[e]=o*tanhf(cst[e]);
      }
      // h_seq output (normal layout)
      float* hw = out + ((size_t)t*NB + 16*mt + g)*NH + 8*cta + 2*tg;
      *(float2*)hw                = make_float2(hv[0],hv[1]);
      *(float2*)(hw+(size_t)8*NH) = make_float2(hv[2],hv[3]);
      // fragment store: in-warp transpose (cols 2tg,2tg+1 -> tg, tg+4)
      unsigned msk=0xffffffffu;
      int sl0=(lane&~3)|(tg>>1), sl1=sl0+2;
      float u00=__shfl_sync(msk,hv[0],sl0), u01=__shfl_sync(msk,hv[1],sl0);
      float u20=__shfl_sync(msk,hv[2],sl0), u21=__shfl_sync(msk,hv[3],sl0);
      float v00=__shfl_sync(msk,hv[0],sl1), v01=__shfl_sync(msk,hv[1],sl1);
      float v20=__shfl_sync(msk,hv[2],sl1), v21=__shfl_sync(msk,hv[3],sl1);
      int odd=tg&1;
      float4 fr = make_float4(tf32f(odd?u01:u00), tf32f(odd?u21:u20),
                              tf32f(odd?v01:v00), tf32f(odd?v21:v20));
      ((float4*)(g_hfrag + (size_t)t*NB*NH))[cta*128 + mt*32 + lane] = fr;
      __threadfence();                    // release: frag visible before flag
    }
    __syncthreads();                      // barrier 3: writers done
    if(tid==0) atomicAdd(&g_flags[t],1);
  }

  if(kh==0){  // tails: h_final (== h_seq[511]) then c_final
    float* ho = out + HSEQ + (size_t)(16*mt+g)*NH + 8*cta + 2*tg;
    float* co = ho + (size_t)NB*NH;
    *(float2*)ho                = make_float2(hv[0],hv[1]);
    *(float2*)(ho+(size_t)8*NH) = make_float2(hv[2],hv[3]);
    *(float2*)co                = make_float2(cst[0],cst[1]);
    *(float2*)(co+(size_t)8*NH) = make_float2(cst[2],cst[3]);
  }
}

extern "C" void kernel_launch(void* const* d_in, const int* in_sizes, int n_in,
                              void* d_out, int out_size){
  const float* x =(const float*)d_in[0];
  const float* W1=(const float*)d_in[1];  const float* b1=(const float*)d_in[2];
  const float* W2=(const float*)d_in[3];  const float* b2=(const float*)d_in[4];
  const float* W3=(const float*)d_in[5];  const float* b3=(const float*)d_in[6];
  const float* W4=(const float*)d_in[7];  const float* b4=(const float*)d_in[8];
  const float* W5=(const float*)d_in[9];  const float* b5=(const float*)d_in[10];
  const float* W6=(const float*)d_in[11]; const float* b6=(const float*)d_in[12];
  const float* W7=(const float*)d_in[13]; const float* b7=(const float*)d_in[14];
  const float* W8=(const float*)d_in[15]; const float* b8=(const float*)d_in[16];
  float* out=(float*)d_out;

  cudaFuncSetAttribute(lstm_rec, cudaFuncAttributeMaxDynamicSharedMemorySize, 155648);

  dim3 grid(64,256);
  xg_gemm<<<grid,256>>>(x, W1,W3,W5,W7, b1,b3,b5,b7, b2,b4,b6,b8);
  lstm_rec<<<128,512,155648>>>(W2,W4,W6,W8, out);
}